// round 6
// baseline (speedup 1.0000x reference)
#include <cuda_runtime.h>

// out[i, h=n*7+o, m] = sum_{j<48,k<3} W[i,j,k] * x[j, n*7+(o+k-1), m]
//   (term dropped when o+k-1 outside [0,7))
// x: (48,56,56) f32   W: (192,48,3) f32   out: (192,56,56) f32

#define JCH 48
#define KTAP 3
#define MW 56
#define MH 28            // m-half width
#define MHP 32           // padded m-half (float4-friendly)
#define BI 32            // output channels per block
#define WSS 34           // ws row stride (even -> 8B-aligned float2 loads)
#define NTHREADS 128

__global__ __launch_bounds__(NTHREADS, 5)
void fold_conv_kernel(const float* __restrict__ x,
                      const float* __restrict__ W,
                      float* __restrict__ out)
{
    extern __shared__ float sm[];
    float* xs = sm;                         // [KTAP*JCH][MHP] = 144*32 floats (18 KB)
    float* ws = sm + KTAP * JCH * MHP;      // [JCH*KTAP][WSS] = 144*34 floats (19.1 KB)

    const int tid = threadIdx.x;
    const int h     = blockIdx.x;           // 0..55
    const int n     = h / 7;
    const int o     = h - n * 7;
    const int i0    = blockIdx.y * BI;      // 0..160 step 32
    const int mbase = blockIdx.z * MH;      // 0 or 28

    // ---- load x slab: 144 rows x 8 float4 (7 real + 1 pad), coalesced ----
    {
        float4* xs4 = (float4*)xs;
        #pragma unroll
        for (int it = 0; it < (KTAP * JCH * 8) / NTHREADS; ++it) {   // 9 iters
            int idx = tid + it * NTHREADS;          // 0..1151
            int row = idx >> 3;                     // k*48+j
            int s   = idx & 7;                      // float4 slot (s==7 -> pad)
            int k   = row / JCH;
            int j   = row - k * JCH;
            int r   = o + k - 1;
            float4 v = make_float4(0.f, 0.f, 0.f, 0.f);
            if (r >= 0 && r < 7 && s < 7)
                v = *(const float4*)&x[(j * 56 + n * 7 + r) * 56 + mbase + s * 4];
            xs4[idx] = v;
        }
    }
    // ---- load W tile: float4 gmem reads, transposed scatter to [jk][ii] ----
    #pragma unroll
    for (int it = 0; it < (BI * 36) / NTHREADS; ++it) {              // 9 iters
        int idx = tid + it * NTHREADS;              // 0..1151 (f4 chunks)
        int ii  = idx / 36;
        int q   = idx - ii * 36;                    // f4 slot within 144
        float4 v = *(const float4*)&W[(i0 + ii) * (JCH * KTAP) + q * 4];
        ws[(q * 4 + 0) * WSS + ii] = v.x;
        ws[(q * 4 + 1) * WSS + ii] = v.y;
        ws[(q * 4 + 2) * WSS + ii] = v.z;
        ws[(q * 4 + 3) * WSS + ii] = v.w;
    }
    __syncthreads();

    // ---- register-tiled mainloop: each thread computes 2i x 4m ----
    const int mg  = tid & 7;                // 8 m-groups (mg==7 -> padding, discarded)
    const int ig  = tid >> 3;               // 16 i-groups
    const int m0  = mg * 4;
    const int ii0 = ig * 2;

    float acc[2][4];
    #pragma unroll
    for (int a = 0; a < 2; ++a)
        #pragma unroll
        for (int b = 0; b < 4; ++b)
            acc[a][b] = 0.0f;

    #pragma unroll 4
    for (int j = 0; j < JCH; ++j) {
        float4 xv[KTAP];
        float2 wv[KTAP];
        #pragma unroll
        for (int k = 0; k < KTAP; ++k) {
            xv[k] = *(const float4*)&xs[(k * JCH + j) * MHP + m0];
            wv[k] = *(const float2*)&ws[(j * 3 + k) * WSS + ii0];
        }
        #pragma unroll
        for (int k = 0; k < KTAP; ++k) {
            acc[0][0] = fmaf(wv[k].x, xv[k].x, acc[0][0]);
            acc[0][1] = fmaf(wv[k].x, xv[k].y, acc[0][1]);
            acc[0][2] = fmaf(wv[k].x, xv[k].z, acc[0][2]);
            acc[0][3] = fmaf(wv[k].x, xv[k].w, acc[0][3]);
            acc[1][0] = fmaf(wv[k].y, xv[k].x, acc[1][0]);
            acc[1][1] = fmaf(wv[k].y, xv[k].y, acc[1][1]);
            acc[1][2] = fmaf(wv[k].y, xv[k].z, acc[1][2]);
            acc[1][3] = fmaf(wv[k].y, xv[k].w, acc[1][3]);
        }
    }

    // ---- store (skip padded m-group; 16B-aligned float4) ----
    if (mg < 7) {
        #pragma unroll
        for (int a = 0; a < 2; ++a) {
            const int i = i0 + ii0 + a;
            float4 v = {acc[a][0], acc[a][1], acc[a][2], acc[a][3]};
            *(float4*)&out[(i * 56 + h) * 56 + mbase + m0] = v;
        }
    }
}

extern "C" void kernel_launch(void* const* d_in, const int* in_sizes, int n_in,
                              void* d_out, int out_size)
{
    const float* x = (const float*)d_in[0];   // 48*56*56
    const float* W = (const float*)d_in[1];   // 192*48*3
    float* out = (float*)d_out;               // 192*56*56

    const int smem = (KTAP * JCH * MHP + JCH * KTAP * WSS) * (int)sizeof(float); // 38016 B
    dim3 grid(56, 6, 2);
    fold_conv_kernel<<<grid, NTHREADS, smem>>>(x, W, out);
}